// round 2
// baseline (speedup 1.0000x reference)
#include <cuda_runtime.h>
#include <math.h>

#define N_CLS   3
#define N_YAW   2
#define NY      160
#define NX      160
#define N_ANCH  (N_YAW * NY * NX)   // 51200 anchors per class
#define N_BOX   32
#define CELLS_Y0 (NY * NX)          // 25600 (yaw-0 cells, for M_reg)

// output layout (concatenated flattened float32 in return order)
#define OFF_GCLS 0
#define SZ_GCLS  (N_CLS * N_ANCH)              // 153600
#define OFF_GREG (OFF_GCLS + SZ_GCLS)
#define SZ_GREG  (N_CLS * N_ANCH * 7)          // 1075200
#define OFF_MCLS (OFF_GREG + SZ_GREG)
#define SZ_MCLS  (N_ANCH)                      // 51200
#define OFF_MREG (OFF_MCLS + SZ_MCLS)
#define SZ_MREG  (N_CLS * CELLS_Y0)            // 76800

// scratch: compacted IoU matrix [cls*32+slot][anchor] (only cnt[cls] slots used
// per class; each box belongs to exactly one class so <=32 rows are live) and
// per-global-box highest IoU (bit pattern of positive float, atomicMax-able).
__device__ float        g_iou[(size_t)N_CLS * N_BOX * N_ANCH];
__device__ unsigned int g_high[N_BOX];

__constant__ float c_low[3]    = {0.45f, 0.35f, 0.35f};
__constant__ float c_highth[3] = {0.60f, 0.50f, 0.50f};

struct V2 { float x, y; };

// Intersection area of two rotated rectangles via Sutherland-Hodgman.
__device__ __forceinline__ float rect_inter_area(
    float cx1, float cy1, float hw1, float hl1, float c1, float s1,
    float cx2, float cy2, float hw2, float hl2, float c2, float s2)
{
    float ux2 = c2 * hw2, uy2 = s2 * hw2;
    float vx2 = -s2 * hl2, vy2 = c2 * hl2;
    V2 P[8], Q[8];
    P[0] = {cx2 + ux2 + vx2, cy2 + uy2 + vy2};
    P[1] = {cx2 + ux2 - vx2, cy2 + uy2 - vy2};
    P[2] = {cx2 - ux2 - vx2, cy2 - uy2 - vy2};
    P[3] = {cx2 - ux2 + vx2, cy2 - uy2 + vy2};
    int n = 4;

    float ux1 = c1 * hw1, uy1 = s1 * hw1;
    float vx1 = -s1 * hl1, vy1 = c1 * hl1;
    V2 CC[4];
    CC[0] = {cx1 + ux1 + vx1, cy1 + uy1 + vy1};
    CC[1] = {cx1 + ux1 - vx1, cy1 + uy1 - vy1};
    CC[2] = {cx1 - ux1 - vx1, cy1 - uy1 - vy1};
    CC[3] = {cx1 - ux1 + vx1, cy1 - uy1 + vy1};

    V2* src = P;
    V2* dst = Q;
    for (int e = 0; e < 4; e++) {
        V2 A = CC[e];
        V2 B = CC[(e + 1) & 3];
        float ex = B.x - A.x, ey = B.y - A.y;
        int m = 0;
        V2 pprev = src[n - 1];
        float dprev = ex * (pprev.y - A.y) - ey * (pprev.x - A.x);
        for (int i = 0; i < n; i++) {
            V2 p = src[i];
            float d = ex * (p.y - A.y) - ey * (p.x - A.x);
            bool inp = (d <= 0.0f), inprev = (dprev <= 0.0f);
            if (inprev != inp) {
                float t = dprev / (dprev - d);
                if (m < 8) { dst[m].x = pprev.x + t * (p.x - pprev.x);
                             dst[m].y = pprev.y + t * (p.y - pprev.y); m++; }
            }
            if (inp) { if (m < 8) dst[m++] = p; }
            dprev = d; pprev = p;
        }
        n = m;
        if (n == 0) return 0.0f;
        V2* tmp = src; src = dst; dst = tmp;
    }

    float ar = 0.0f;
    for (int i = 0; i < n; i++) {
        V2 p = src[i];
        V2 q = src[(i + 1 == n) ? 0 : (i + 1)];
        ar += p.x * q.y - q.x * p.y;
    }
    return 0.5f * fabsf(ar);
}

__global__ void iou_kernel(const float* __restrict__ boxes,
                           const float* __restrict__ anchors,
                           const int* __restrict__ cidx)
{
    const int cls = blockIdx.y;
    const int a = blockIdx.x * blockDim.x + threadIdx.x;

    // compacted per-class box list (ascending global order) + params
    __shared__ float sb[8][N_BOX];    // x, y, hw, hl, cos, sin, radius, area
    __shared__ int   s_box[N_BOX];    // slot -> global box index
    __shared__ int   s_cnt;
    if (threadIdx.x == 0) {
        int cnt = 0;
        for (int b = 0; b < N_BOX; b++) {
            if (cidx[b] == cls) {
                float x = boxes[b * 7 + 0];
                float y = boxes[b * 7 + 1];
                float w = boxes[b * 7 + 3];
                float l = boxes[b * 7 + 4];
                float yaw = boxes[b * 7 + 6];
                sb[0][cnt] = x; sb[1][cnt] = y;
                sb[2][cnt] = 0.5f * w; sb[3][cnt] = 0.5f * l;
                sb[4][cnt] = cosf(yaw); sb[5][cnt] = sinf(yaw);
                sb[6][cnt] = 0.5f * sqrtf(w * w + l * l);
                sb[7][cnt] = w * l;
                s_box[cnt] = b;
                cnt++;
            }
        }
        s_cnt = cnt;
    }
    __syncthreads();
    if (a >= N_ANCH) return;

    const int cnt = s_cnt;
    const float* A = anchors + ((size_t)cls * N_ANCH + a) * 7;
    float ax = A[0], ay = A[1], aw = A[3], al = A[4], ayaw = A[6];
    float ac = cosf(ayaw), asn = sinf(ayaw);
    float ahw = 0.5f * aw, ahl = 0.5f * al;
    float arad = 0.5f * sqrtf(aw * aw + al * al);
    float aarea = aw * al;

    for (int s = 0; s < cnt; s++) {
        float iou = 0.0f;
        float dx = sb[0][s] - ax, dy = sb[1][s] - ay;
        float rr = sb[6][s] + arad;
        if (dx * dx + dy * dy <= rr * rr) {
            float inter = rect_inter_area(
                sb[0][s], sb[1][s], sb[2][s], sb[3][s], sb[4][s], sb[5][s],
                ax, ay, ahw, ahl, ac, asn);
            float uni = sb[7][s] + aarea - inter;
            iou = inter / fmaxf(uni, 1e-8f);
            iou = fminf(fmaxf(iou, 0.0f), 1.0f);
            if (iou > 0.0f)
                atomicMax(&g_high[s_box[s]], __float_as_uint(iou));
        }
        g_iou[((size_t)(cls * N_BOX + s)) * N_ANCH + a] = iou;
    }
}

__global__ void combine_kernel(const float* __restrict__ boxes,
                               const float* __restrict__ anchors,
                               const int* __restrict__ cidx,
                               float* __restrict__ out)
{
    const int a = blockIdx.x * blockDim.x + threadIdx.x;

    __shared__ int          s_box[N_CLS][N_BOX];
    __shared__ int          s_cnt[N_CLS];
    __shared__ unsigned int s_high[N_BOX];
    if (threadIdx.x == 0) {
        int cnt[N_CLS] = {0, 0, 0};
        for (int b = 0; b < N_BOX; b++) {
            int c = cidx[b];
            s_box[c][cnt[c]++] = b;
        }
        s_cnt[0] = cnt[0]; s_cnt[1] = cnt[1]; s_cnt[2] = cnt[2];
    }
    if (threadIdx.x < N_BOX) s_high[threadIdx.x] = g_high[threadIdx.x];
    __syncthreads();
    if (a >= N_ANCH) return;

    int lab[N_CLS], midx[N_CLS];

    #pragma unroll
    for (int c = 0; c < N_CLS; c++) {
        float maxv = -1.0f;     // invalid entries in reference are -1.0
        int idx = 0;
        bool lq = false;
        const int cnt = s_cnt[c];
        for (int s = 0; s < cnt; s++) {
            float v = g_iou[((size_t)(c * N_BOX + s)) * N_ANCH + a];
            if (v > maxv) { maxv = v; idx = s_box[c][s]; }  // first-argmax
            if (v > 0.0f && __float_as_uint(v) == s_high[s_box[c][s]]) lq = true;
        }
        int L = (maxv >= c_highth[c]) ? 1 : ((maxv >= c_low[c]) ? -1 : 0);
        if (lq) L = 1;
        lab[c] = L;
        midx[c] = idx;
    }

    // ambiguous: >1 class positive -> all -1
    int pos = (lab[0] == 1) + (lab[1] == 1) + (lab[2] == 1);
    if (pos > 1) { lab[0] = -1; lab[1] = -1; lab[2] = -1; }
    bool neg = (lab[0] == 0) || (lab[1] == 0) || (lab[2] == 0);
    int pos2 = (lab[0] == 1) + (lab[1] == 1) + (lab[2] == 1);
    bool positive = (pos2 == 1);
    if (neg && !positive) { lab[0] = 0; lab[1] = 0; lab[2] = 0; }
    bool all_m1 = (lab[0] == -1) && (lab[1] == -1) && (lab[2] == -1);
    float loss_mask = all_m1 ? 0.0f : 1.0f;
    #pragma unroll
    for (int c = 0; c < N_CLS; c++)
        if (lab[c] == -1) lab[c] = 0;

    float* G_cls = out + OFF_GCLS;
    float* G_reg = out + OFF_GREG;
    float* M_cls = out + OFF_MCLS;
    float* M_reg = out + OFF_MREG;

    #pragma unroll
    for (int c = 0; c < N_CLS; c++) {
        G_cls[c * N_ANCH + a] = (float)lab[c];

        float vals[7] = {0.f, 0.f, 0.f, 0.f, 0.f, 0.f, 0.f};
        if (lab[c] == 1) {
            const float* B = boxes + midx[c] * 7;
            const float* A = anchors + ((size_t)c * N_ANCH + a) * 7;
            float nrm = sqrtf(A[3] * A[3] + A[4] * A[4]);
            vals[0] = (B[0] - A[0]) / nrm;
            vals[1] = (B[1] - A[1]) / nrm;
            vals[2] = (B[2] - A[2]) / A[5];
            vals[3] = logf(B[3] / A[3]);
            vals[4] = logf(B[4] / A[4]);
            vals[5] = logf(B[5] / A[5]);
            vals[6] = B[6] - A[6];
        }
        size_t base = ((size_t)c * N_ANCH + a) * 7;
        #pragma unroll
        for (int k = 0; k < 7; k++) G_reg[base + k] = vals[k];

        if (a < CELLS_Y0) M_reg[c * CELLS_Y0 + a] = (float)lab[c];
    }
    M_cls[a] = loss_mask;
}

extern "C" void kernel_launch(void* const* d_in, const int* in_sizes, int n_in,
                              void* d_out, int out_size)
{
    const float* boxes = nullptr;
    const float* anchors = nullptr;
    const int* cidx = nullptr;
    for (int i = 0; i < n_in; i++) {
        if (in_sizes[i] == N_BOX * 7)               boxes = (const float*)d_in[i];
        else if (in_sizes[i] == N_CLS * N_ANCH * 7) anchors = (const float*)d_in[i];
        else if (in_sizes[i] == N_BOX)              cidx = (const int*)d_in[i];
    }
    float* out = (float*)d_out;

    // zero per-box highest-IoU accumulators via a memset node (no kernel launch)
    void* high_ptr = nullptr;
    cudaGetSymbolAddress(&high_ptr, g_high);
    cudaMemsetAsync(high_ptr, 0, N_BOX * sizeof(unsigned int));

    dim3 gridA((N_ANCH + 255) / 256, N_CLS);
    iou_kernel<<<gridA, 256>>>(boxes, anchors, cidx);

    combine_kernel<<<(N_ANCH + 255) / 256, 256>>>(boxes, anchors, cidx, out);
}

// round 3
// speedup vs baseline: 1.0959x; 1.0959x over previous
#include <cuda_runtime.h>
#include <math.h>

#define N_CLS   3
#define N_YAW   2
#define NY      160
#define NX      160
#define N_ANCH  (N_YAW * NY * NX)   // 51200 anchor positions per class
#define N_BOX   32
#define CELLS_Y0 (NY * NX)          // 25600

// output layout (concatenated flattened float32 in return order)
#define OFF_GCLS 0
#define SZ_GCLS  (N_CLS * N_ANCH)
#define OFF_GREG (OFF_GCLS + SZ_GCLS)
#define SZ_GREG  (N_CLS * N_ANCH * 7)
#define OFF_MCLS (OFF_GREG + SZ_GREG)
#define SZ_MCLS  (N_ANCH)
#define OFF_MREG (OFF_MCLS + SZ_MCLS)
#define SZ_MREG  (N_CLS * CELLS_Y0)

// scratch: anchor-major IoU matrix [position][box] as float4 (8 per position),
// plus per-box highest positive IoU bit pattern (atomicMax on uint).
__device__ float4       g_iou4[(size_t)N_ANCH * 8];   // 6.5 MB
__device__ unsigned int g_high[N_BOX];

__constant__ float c_low[3]    = {0.45f, 0.35f, 0.35f};
__constant__ float c_highth[3] = {0.60f, 0.50f, 0.50f};

struct V2 { float x, y; };

// Intersection area of two rotated rectangles via Sutherland-Hodgman.
__device__ __forceinline__ float rect_inter_area(
    float cx1, float cy1, float hw1, float hl1, float c1, float s1,
    float cx2, float cy2, float hw2, float hl2, float c2, float s2)
{
    float ux2 = c2 * hw2, uy2 = s2 * hw2;
    float vx2 = -s2 * hl2, vy2 = c2 * hl2;
    V2 P[8], Q[8];
    P[0] = {cx2 + ux2 + vx2, cy2 + uy2 + vy2};
    P[1] = {cx2 + ux2 - vx2, cy2 + uy2 - vy2};
    P[2] = {cx2 - ux2 - vx2, cy2 - uy2 - vy2};
    P[3] = {cx2 - ux2 + vx2, cy2 - uy2 + vy2};
    int n = 4;

    float ux1 = c1 * hw1, uy1 = s1 * hw1;
    float vx1 = -s1 * hl1, vy1 = c1 * hl1;
    V2 CC[4];
    CC[0] = {cx1 + ux1 + vx1, cy1 + uy1 + vy1};
    CC[1] = {cx1 + ux1 - vx1, cy1 + uy1 - vy1};
    CC[2] = {cx1 - ux1 - vx1, cy1 - uy1 - vy1};
    CC[3] = {cx1 - ux1 + vx1, cy1 - uy1 + vy1};

    V2* src = P;
    V2* dst = Q;
    for (int e = 0; e < 4; e++) {
        V2 A = CC[e];
        V2 B = CC[(e + 1) & 3];
        float ex = B.x - A.x, ey = B.y - A.y;
        int m = 0;
        V2 pprev = src[n - 1];
        float dprev = ex * (pprev.y - A.y) - ey * (pprev.x - A.x);
        for (int i = 0; i < n; i++) {
            V2 p = src[i];
            float d = ex * (p.y - A.y) - ey * (p.x - A.x);
            bool inp = (d <= 0.0f), inprev = (dprev <= 0.0f);
            if (inprev != inp) {
                float t = dprev / (dprev - d);
                if (m < 8) { dst[m].x = pprev.x + t * (p.x - pprev.x);
                             dst[m].y = pprev.y + t * (p.y - pprev.y); m++; }
            }
            if (inp) { if (m < 8) dst[m++] = p; }
            dprev = d; pprev = p;
        }
        n = m;
        if (n == 0) return 0.0f;
        V2* tmp = src; src = dst; dst = tmp;
    }

    float ar = 0.0f;
    for (int i = 0; i < n; i++) {
        V2 p = src[i];
        V2 q = src[(i + 1 == n) ? 0 : (i + 1)];
        ar += p.x * q.y - q.x * p.y;
    }
    return 0.5f * fabsf(ar);
}

// box params in shared
__shared__ float sbx[N_BOX], sby[N_BOX], sbhw[N_BOX], sbhl[N_BOX],
                 sbc[N_BOX], sbs[N_BOX], sbr[N_BOX], sbar[N_BOX];
__shared__ int   s_cls[N_BOX];

__device__ __forceinline__ float pair_iou(
    int b, float ax, float ay, float ac, float as_,
    float ahw0, float ahl0, float ar0, float aa0,
    float ahw1, float ahl1, float ar1, float aa1,
    float ahw2, float ahl2, float ar2, float aa2)
{
    int c = s_cls[b];                           // uniform across threads
    float ahw = (c == 0) ? ahw0 : (c == 1) ? ahw1 : ahw2;
    float ahl = (c == 0) ? ahl0 : (c == 1) ? ahl1 : ahl2;
    float arad = (c == 0) ? ar0 : (c == 1) ? ar1 : ar2;
    float aarea = (c == 0) ? aa0 : (c == 1) ? aa1 : aa2;

    float iou = 0.0f;
    float dx = sbx[b] - ax, dy = sby[b] - ay;
    float rr = sbr[b] + arad;
    if (dx * dx + dy * dy <= rr * rr) {
        float inter = rect_inter_area(
            sbx[b], sby[b], sbhw[b], sbhl[b], sbc[b], sbs[b],
            ax, ay, ahw, ahl, ac, as_);
        float uni = sbar[b] + aarea - inter;
        iou = inter / fmaxf(uni, 1e-8f);
        iou = fminf(fmaxf(iou, 0.0f), 1.0f);
        if (iou > 0.0f)
            atomicMax(&g_high[b], __float_as_uint(iou));
    }
    return iou;
}

__global__ void iou_kernel(const float* __restrict__ boxes,
                           const float* __restrict__ anchors,
                           const int* __restrict__ cidx)
{
    if (threadIdx.x < N_BOX) {
        int b = threadIdx.x;
        float x = boxes[b * 7 + 0];
        float y = boxes[b * 7 + 1];
        float w = boxes[b * 7 + 3];
        float l = boxes[b * 7 + 4];
        float yaw = boxes[b * 7 + 6];
        sbx[b] = x; sby[b] = y;
        sbhw[b] = 0.5f * w; sbhl[b] = 0.5f * l;
        sbc[b] = cosf(yaw); sbs[b] = sinf(yaw);
        sbr[b] = 0.5f * sqrtf(w * w + l * l);
        sbar[b] = w * l;
        s_cls[b] = cidx[b];
    }
    __syncthreads();

    const int a = blockIdx.x * blockDim.x + threadIdx.x;
    if (a >= N_ANCH) return;

    // x,y,yaw shared across classes; w,l per class
    const float* A0 = anchors + (size_t)a * 7;
    float ax = A0[0], ay = A0[1], ayaw = A0[6];
    float ac = cosf(ayaw), as_ = sinf(ayaw);

    float ahw[3], ahl[3], arad[3], aarea[3];
    #pragma unroll
    for (int c = 0; c < N_CLS; c++) {
        const float* A = anchors + ((size_t)c * N_ANCH + a) * 7;
        float w = A[3], l = A[4];
        ahw[c] = 0.5f * w; ahl[c] = 0.5f * l;
        arad[c] = 0.5f * sqrtf(w * w + l * l);
        aarea[c] = w * l;
    }

    for (int bb = 0; bb < N_BOX; bb += 4) {
        float4 r;
        r.x = pair_iou(bb + 0, ax, ay, ac, as_,
                       ahw[0], ahl[0], arad[0], aarea[0],
                       ahw[1], ahl[1], arad[1], aarea[1],
                       ahw[2], ahl[2], arad[2], aarea[2]);
        r.y = pair_iou(bb + 1, ax, ay, ac, as_,
                       ahw[0], ahl[0], arad[0], aarea[0],
                       ahw[1], ahl[1], arad[1], aarea[1],
                       ahw[2], ahl[2], arad[2], aarea[2]);
        r.z = pair_iou(bb + 2, ax, ay, ac, as_,
                       ahw[0], ahl[0], arad[0], aarea[0],
                       ahw[1], ahl[1], arad[1], aarea[1],
                       ahw[2], ahl[2], arad[2], aarea[2]);
        r.w = pair_iou(bb + 3, ax, ay, ac, as_,
                       ahw[0], ahl[0], arad[0], aarea[0],
                       ahw[1], ahl[1], arad[1], aarea[1],
                       ahw[2], ahl[2], arad[2], aarea[2]);
        g_iou4[(size_t)a * 8 + (bb >> 2)] = r;
    }
}

__global__ void combine_kernel(const float* __restrict__ boxes,
                               const float* __restrict__ anchors,
                               const int* __restrict__ cidx,
                               float* __restrict__ out)
{
    __shared__ int          c_cls[N_BOX];
    __shared__ unsigned int c_high[N_BOX];
    __shared__ float        c_box[N_BOX][7];
    if (threadIdx.x < N_BOX) {
        int b = threadIdx.x;
        c_cls[b] = cidx[b];
        c_high[b] = g_high[b];
        #pragma unroll
        for (int k = 0; k < 7; k++) c_box[b][k] = boxes[b * 7 + k];
    }
    __syncthreads();

    const int a = blockIdx.x * blockDim.x + threadIdx.x;
    if (a >= N_ANCH) return;

    // 8 independent 128-bit loads -> full MLP
    float iou[N_BOX];
    #pragma unroll
    for (int k = 0; k < 8; k++) {
        float4 v = g_iou4[(size_t)a * 8 + k];
        iou[4 * k + 0] = v.x;
        iou[4 * k + 1] = v.y;
        iou[4 * k + 2] = v.z;
        iou[4 * k + 3] = v.w;
    }

    int lab[N_CLS], midx[N_CLS];
    #pragma unroll
    for (int c = 0; c < N_CLS; c++) {
        float maxv = -1.0f;   // matches reference's -1 mask for non-class rows
        int idx = 0;
        bool lq = false;
        #pragma unroll
        for (int b = 0; b < N_BOX; b++) {
            if (c_cls[b] == c) {          // uniform predicate
                float v = iou[b];
                if (v > maxv) { maxv = v; idx = b; }   // first-argmax
                if (v > 0.0f && __float_as_uint(v) == c_high[b]) lq = true;
            }
        }
        int L = (maxv >= c_highth[c]) ? 1 : ((maxv >= c_low[c]) ? -1 : 0);
        if (lq) L = 1;
        lab[c] = L;
        midx[c] = idx;
    }

    int pos = (lab[0] == 1) + (lab[1] == 1) + (lab[2] == 1);
    if (pos > 1) { lab[0] = -1; lab[1] = -1; lab[2] = -1; }
    bool neg = (lab[0] == 0) || (lab[1] == 0) || (lab[2] == 0);
    int pos2 = (lab[0] == 1) + (lab[1] == 1) + (lab[2] == 1);
    bool positive = (pos2 == 1);
    if (neg && !positive) { lab[0] = 0; lab[1] = 0; lab[2] = 0; }
    bool all_m1 = (lab[0] == -1) && (lab[1] == -1) && (lab[2] == -1);
    float loss_mask = all_m1 ? 0.0f : 1.0f;
    #pragma unroll
    for (int c = 0; c < N_CLS; c++)
        if (lab[c] == -1) lab[c] = 0;

    float* G_cls = out + OFF_GCLS;
    float* G_reg = out + OFF_GREG;
    float* M_cls = out + OFF_MCLS;
    float* M_reg = out + OFF_MREG;

    #pragma unroll
    for (int c = 0; c < N_CLS; c++) {
        G_cls[c * N_ANCH + a] = (float)lab[c];

        float vals[7] = {0.f, 0.f, 0.f, 0.f, 0.f, 0.f, 0.f};
        if (lab[c] == 1) {
            const float* B = c_box[midx[c]];
            const float* A = anchors + ((size_t)c * N_ANCH + a) * 7;
            float nrm = sqrtf(A[3] * A[3] + A[4] * A[4]);
            vals[0] = (B[0] - A[0]) / nrm;
            vals[1] = (B[1] - A[1]) / nrm;
            vals[2] = (B[2] - A[2]) / A[5];
            vals[3] = logf(B[3] / A[3]);
            vals[4] = logf(B[4] / A[4]);
            vals[5] = logf(B[5] / A[5]);
            vals[6] = B[6] - A[6];
        }
        size_t base = ((size_t)c * N_ANCH + a) * 7;
        #pragma unroll
        for (int k = 0; k < 7; k++) G_reg[base + k] = vals[k];

        if (a < CELLS_Y0) M_reg[c * CELLS_Y0 + a] = (float)lab[c];
    }
    M_cls[a] = loss_mask;
}

extern "C" void kernel_launch(void* const* d_in, const int* in_sizes, int n_in,
                              void* d_out, int out_size)
{
    const float* boxes = nullptr;
    const float* anchors = nullptr;
    const int* cidx = nullptr;
    for (int i = 0; i < n_in; i++) {
        if (in_sizes[i] == N_BOX * 7)               boxes = (const float*)d_in[i];
        else if (in_sizes[i] == N_CLS * N_ANCH * 7) anchors = (const float*)d_in[i];
        else if (in_sizes[i] == N_BOX)              cidx = (const int*)d_in[i];
    }
    float* out = (float*)d_out;

    void* high_ptr = nullptr;
    cudaGetSymbolAddress(&high_ptr, g_high);
    cudaMemsetAsync(high_ptr, 0, N_BOX * sizeof(unsigned int));

    iou_kernel<<<(N_ANCH + 255) / 256, 256>>>(boxes, anchors, cidx);
    combine_kernel<<<(N_ANCH + 255) / 256, 256>>>(boxes, anchors, cidx, out);
}